// round 2
// baseline (speedup 1.0000x reference)
#include <cuda_runtime.h>
#include <math.h>

#define HIDDEN  256
#define GATES   1024        // 4 * HIDDEN
#define HORIZON 24
#define BATCH   32768
#define TB      16          // batch rows per block
#define THREADS 256

// Transposed recurrent weights: WT[k*GATES + r] = W_hh[r*HIDDEN + k]
// 1 MB static device scratch (allowed; no dynamic allocation).
__device__ float g_WT[HIDDEN * GATES];

__global__ void transpose_whh(const float* __restrict__ W) {
    int idx = blockIdx.x * blockDim.x + threadIdx.x;
    if (idx < HIDDEN * GATES) {
        int k = idx >> 10;          // 0..255
        int r = idx & (GATES - 1);  // 0..1023
        g_WT[idx] = W[r * HIDDEN + k];
    }
}

__device__ __forceinline__ float sigmoidf_(float v) {
    return 1.0f / (1.0f + expf(-v));
}

__global__ void __launch_bounds__(THREADS, 1)
lstm_fused_kernel(const float* __restrict__ x,
                  const float* __restrict__ h0,
                  const float* __restrict__ c0,
                  const float* __restrict__ W_ih,
                  const float* __restrict__ b_ih,
                  const float* __restrict__ b_hh,
                  const float* __restrict__ fc_W,
                  const float* __restrict__ fc_b,
                  float* __restrict__ out)
{
    // h double buffer, b-major: hs[buf][b_local*HIDDEN + k]
    __shared__ float hs[2][TB * HIDDEN];
    __shared__ float out_s[TB];

    const int tid = threadIdx.x;
    const int jt  = tid & 63;   // hidden-unit tile index (0..63) -> units 4*jt..4*jt+3
    const int bt  = tid >> 6;   // batch  tile index (0..3)      -> rows  4*bt..4*bt+3
    const int j0  = jt * 4;
    const int b0  = bt * 4;                 // local batch base
    const int gb0 = blockIdx.x * TB;        // global batch base

    // ---- prologue: load h tile into shared (coalesced) ----
    for (int i = tid; i < TB * HIDDEN; i += THREADS)
        hs[0][i] = h0[(size_t)gb0 * HIDDEN + i];
    if (tid < TB) out_s[tid] = 0.0f;

    // ---- per-thread persistent state ----
    float creg[4][4];           // cell state, lives in registers across all steps
    float xv[4];
    #pragma unroll
    for (int i = 0; i < 4; i++) {
        xv[i] = x[gb0 + b0 + i];
        #pragma unroll
        for (int d = 0; d < 4; d++)
            creg[i][d] = c0[(size_t)(gb0 + b0 + i) * HIDDEN + j0 + d];
    }

    // input-path constants: x_gates[b][g,j] = x[b]*W_ih[g*H+j] + b_ih[..] + b_hh[..]
    float wih[4][4], bias[4][4];
    #pragma unroll
    for (int g = 0; g < 4; g++) {
        #pragma unroll
        for (int d = 0; d < 4; d++) {
            int r = g * HIDDEN + j0 + d;
            wih[g][d]  = W_ih[r];
            bias[g][d] = b_ih[r] + b_hh[r];
        }
    }
    float fcw[4];
    #pragma unroll
    for (int d = 0; d < 4; d++) fcw[d] = fc_W[j0 + d];
    const float fcb = fc_b[0];

    __syncthreads();

    const float4* __restrict__ WT4 = reinterpret_cast<const float4*>(g_WT);

    int cur = 0;
    for (int t = 0; t < HORIZON; t++) {
        // accumulators [gate][batch][unit] initialized with the constant input path
        float acc[4][4][4];
        #pragma unroll
        for (int g = 0; g < 4; g++)
            #pragma unroll
            for (int i = 0; i < 4; i++)
                #pragma unroll
                for (int d = 0; d < 4; d++)
                    acc[g][i][d] = fmaf(xv[i], wih[g][d], bias[g][d]);

        const float* __restrict__ hcur = hs[cur];

        // ---- main GEMM: acc[g][i][d] += WT[k][g*256 + j0+d] * h[b0+i][k] ----
        #pragma unroll 2
        for (int k = 0; k < HIDDEN; k += 4) {
            // 4 h values per batch row (broadcast LDS.128, all lanes same address)
            float ha[4][4];
            #pragma unroll
            for (int i = 0; i < 4; i++) {
                float4 hv = *reinterpret_cast<const float4*>(&hcur[(b0 + i) * HIDDEN + k]);
                ha[i][0] = hv.x; ha[i][1] = hv.y; ha[i][2] = hv.z; ha[i][3] = hv.w;
            }
            #pragma unroll
            for (int kk = 0; kk < 4; kk++) {
                // WT row (k+kk): float4 index = (k+kk)*256 + g*64 + jt  (coalesced per warp)
                const float4* wr = WT4 + (size_t)(k + kk) * 256 + jt;
                float4 w0 = wr[0];
                float4 w1 = wr[64];
                float4 w2 = wr[128];
                float4 w3 = wr[192];
                #pragma unroll
                for (int i = 0; i < 4; i++) {
                    float hvv = ha[i][kk];
                    acc[0][i][0] = fmaf(w0.x, hvv, acc[0][i][0]);
                    acc[0][i][1] = fmaf(w0.y, hvv, acc[0][i][1]);
                    acc[0][i][2] = fmaf(w0.z, hvv, acc[0][i][2]);
                    acc[0][i][3] = fmaf(w0.w, hvv, acc[0][i][3]);
                    acc[1][i][0] = fmaf(w1.x, hvv, acc[1][i][0]);
                    acc[1][i][1] = fmaf(w1.y, hvv, acc[1][i][1]);
                    acc[1][i][2] = fmaf(w1.z, hvv, acc[1][i][2]);
                    acc[1][i][3] = fmaf(w1.w, hvv, acc[1][i][3]);
                    acc[2][i][0] = fmaf(w2.x, hvv, acc[2][i][0]);
                    acc[2][i][1] = fmaf(w2.y, hvv, acc[2][i][1]);
                    acc[2][i][2] = fmaf(w2.z, hvv, acc[2][i][2]);
                    acc[2][i][3] = fmaf(w2.w, hvv, acc[2][i][3]);
                    acc[3][i][0] = fmaf(w3.x, hvv, acc[3][i][0]);
                    acc[3][i][1] = fmaf(w3.y, hvv, acc[3][i][1]);
                    acc[3][i][2] = fmaf(w3.z, hvv, acc[3][i][2]);
                    acc[3][i][3] = fmaf(w3.w, hvv, acc[3][i][3]);
                }
            }
        }

        // ---- elementwise LSTM cell + fc partial ----
        const int nxt = cur ^ 1;
        float partial[4] = {0.f, 0.f, 0.f, 0.f};
        #pragma unroll
        for (int i = 0; i < 4; i++) {
            float hn[4];
            #pragma unroll
            for (int d = 0; d < 4; d++) {
                float ig = sigmoidf_(acc[0][i][d]);
                float fg = sigmoidf_(acc[1][i][d]);
                float gg = tanhf(acc[2][i][d]);
                float og = sigmoidf_(acc[3][i][d]);
                float cn = fmaf(fg, creg[i][d], ig * gg);
                float hv = og * tanhf(cn);
                creg[i][d] = cn;
                hn[d] = hv;
                partial[i] = fmaf(hv, fcw[d], partial[i]);
            }
            // write next-h (STS.128, consecutive 16B per lane -> conflict-free)
            *reinterpret_cast<float4*>(&hs[nxt][(b0 + i) * HIDDEN + j0]) =
                make_float4(hn[0], hn[1], hn[2], hn[3]);
            // warp-level reduction of fc partial (all lanes in a warp share bt)
            float v = partial[i];
            #pragma unroll
            for (int off = 16; off > 0; off >>= 1)
                v += __shfl_xor_sync(0xffffffffu, v, off);
            if ((tid & 31) == 0)
                atomicAdd(&out_s[b0 + i], v);
        }

        __syncthreads();
        if (tid < TB) {
            out[(size_t)t * BATCH + gb0 + tid] = out_s[tid] + fcb;
            out_s[tid] = 0.0f;
        }
        __syncthreads();
        cur = nxt;
    }
}

extern "C" void kernel_launch(void* const* d_in, const int* in_sizes, int n_in,
                              void* d_out, int out_size) {
    const float* x    = (const float*)d_in[0];
    const float* h    = (const float*)d_in[1];
    const float* c    = (const float*)d_in[2];
    const float* W_ih = (const float*)d_in[3];
    const float* W_hh = (const float*)d_in[4];
    const float* b_ih = (const float*)d_in[5];
    const float* b_hh = (const float*)d_in[6];
    const float* fc_W = (const float*)d_in[7];
    const float* fc_b = (const float*)d_in[8];

    transpose_whh<<<(HIDDEN * GATES + 511) / 512, 512>>>(W_hh);
    lstm_fused_kernel<<<BATCH / TB, THREADS>>>(x, h, c, W_ih, b_ih, b_hh,
                                               fc_W, fc_b, (float*)d_out);
}

// round 3
// speedup vs baseline: 1.0000x; 1.0000x over previous
#include <cuda_runtime.h>
#include <math.h>

#define HIDDEN  256
#define GATES   1024        // 4 * HIDDEN
#define HORIZON 24
#define BATCH   32768
#define TB      16          // batch rows per block
#define THREADS 256

// Transposed recurrent weights: WT[k*GATES + r] = W_hh[r*HIDDEN + k]
// 1 MB static device scratch (allowed; no dynamic allocation).
__device__ float g_WT[HIDDEN * GATES];

__global__ void transpose_whh(const float* __restrict__ W) {
    int idx = blockIdx.x * blockDim.x + threadIdx.x;
    if (idx < HIDDEN * GATES) {
        int k = idx >> 10;          // 0..255
        int r = idx & (GATES - 1);  // 0..1023
        g_WT[idx] = W[r * HIDDEN + k];
    }
}

__device__ __forceinline__ float sigmoidf_(float v) {
    return 1.0f / (1.0f + expf(-v));
}

__global__ void __launch_bounds__(THREADS, 1)
lstm_fused_kernel(const float* __restrict__ x,
                  const float* __restrict__ h0,
                  const float* __restrict__ c0,
                  const float* __restrict__ W_ih,
                  const float* __restrict__ b_ih,
                  const float* __restrict__ b_hh,
                  const float* __restrict__ fc_W,
                  const float* __restrict__ fc_b,
                  float* __restrict__ out)
{
    // h double buffer, b-major: hs[buf][b_local*HIDDEN + k]
    __shared__ float hs[2][TB * HIDDEN];
    __shared__ float out_s[TB];

    const int tid = threadIdx.x;
    const int jt  = tid & 63;   // hidden-unit tile index (0..63) -> units 4*jt..4*jt+3
    const int bt  = tid >> 6;   // batch  tile index (0..3)      -> rows  4*bt..4*bt+3
    const int j0  = jt * 4;
    const int b0  = bt * 4;                 // local batch base
    const int gb0 = blockIdx.x * TB;        // global batch base

    // ---- prologue: load h tile into shared (coalesced) ----
    for (int i = tid; i < TB * HIDDEN; i += THREADS)
        hs[0][i] = h0[(size_t)gb0 * HIDDEN + i];
    if (tid < TB) out_s[tid] = 0.0f;

    // ---- per-thread persistent state ----
    float creg[4][4];           // cell state, lives in registers across all steps
    float xv[4];
    #pragma unroll
    for (int i = 0; i < 4; i++) {
        xv[i] = x[gb0 + b0 + i];
        #pragma unroll
        for (int d = 0; d < 4; d++)
            creg[i][d] = c0[(size_t)(gb0 + b0 + i) * HIDDEN + j0 + d];
    }

    // input-path constants: x_gates[b][g,j] = x[b]*W_ih[g*H+j] + b_ih[..] + b_hh[..]
    float wih[4][4], bias[4][4];
    #pragma unroll
    for (int g = 0; g < 4; g++) {
        #pragma unroll
        for (int d = 0; d < 4; d++) {
            int r = g * HIDDEN + j0 + d;
            wih[g][d]  = W_ih[r];
            bias[g][d] = b_ih[r] + b_hh[r];
        }
    }
    float fcw[4];
    #pragma unroll
    for (int d = 0; d < 4; d++) fcw[d] = fc_W[j0 + d];
    const float fcb = fc_b[0];

    __syncthreads();

    const float4* __restrict__ WT4 = reinterpret_cast<const float4*>(g_WT);

    int cur = 0;
    for (int t = 0; t < HORIZON; t++) {
        // accumulators [gate][batch][unit] initialized with the constant input path
        float acc[4][4][4];
        #pragma unroll
        for (int g = 0; g < 4; g++)
            #pragma unroll
            for (int i = 0; i < 4; i++)
                #pragma unroll
                for (int d = 0; d < 4; d++)
                    acc[g][i][d] = fmaf(xv[i], wih[g][d], bias[g][d]);

        const float* __restrict__ hcur = hs[cur];

        // ---- main GEMM: acc[g][i][d] += WT[k][g*256 + j0+d] * h[b0+i][k] ----
        #pragma unroll 2
        for (int k = 0; k < HIDDEN; k += 4) {
            // 4 h values per batch row (broadcast LDS.128, all lanes same address)
            float ha[4][4];
            #pragma unroll
            for (int i = 0; i < 4; i++) {
                float4 hv = *reinterpret_cast<const float4*>(&hcur[(b0 + i) * HIDDEN + k]);
                ha[i][0] = hv.x; ha[i][1] = hv.y; ha[i][2] = hv.z; ha[i][3] = hv.w;
            }
            #pragma unroll
            for (int kk = 0; kk < 4; kk++) {
                // WT row (k+kk): float4 index = (k+kk)*256 + g*64 + jt  (coalesced per warp)
                const float4* wr = WT4 + (size_t)(k + kk) * 256 + jt;
                float4 w0 = wr[0];
                float4 w1 = wr[64];
                float4 w2 = wr[128];
                float4 w3 = wr[192];
                #pragma unroll
                for (int i = 0; i < 4; i++) {
                    float hvv = ha[i][kk];
                    acc[0][i][0] = fmaf(w0.x, hvv, acc[0][i][0]);
                    acc[0][i][1] = fmaf(w0.y, hvv, acc[0][i][1]);
                    acc[0][i][2] = fmaf(w0.z, hvv, acc[0][i][2]);
                    acc[0][i][3] = fmaf(w0.w, hvv, acc[0][i][3]);
                    acc[1][i][0] = fmaf(w1.x, hvv, acc[1][i][0]);
                    acc[1][i][1] = fmaf(w1.y, hvv, acc[1][i][1]);
                    acc[1][i][2] = fmaf(w1.z, hvv, acc[1][i][2]);
                    acc[1][i][3] = fmaf(w1.w, hvv, acc[1][i][3]);
                    acc[2][i][0] = fmaf(w2.x, hvv, acc[2][i][0]);
                    acc[2][i][1] = fmaf(w2.y, hvv, acc[2][i][1]);
                    acc[2][i][2] = fmaf(w2.z, hvv, acc[2][i][2]);
                    acc[2][i][3] = fmaf(w2.w, hvv, acc[2][i][3]);
                    acc[3][i][0] = fmaf(w3.x, hvv, acc[3][i][0]);
                    acc[3][i][1] = fmaf(w3.y, hvv, acc[3][i][1]);
                    acc[3][i][2] = fmaf(w3.z, hvv, acc[3][i][2]);
                    acc[3][i][3] = fmaf(w3.w, hvv, acc[3][i][3]);
                }
            }
        }

        // ---- elementwise LSTM cell + fc partial ----
        const int nxt = cur ^ 1;
        float partial[4] = {0.f, 0.f, 0.f, 0.f};
        #pragma unroll
        for (int i = 0; i < 4; i++) {
            float hn[4];
            #pragma unroll
            for (int d = 0; d < 4; d++) {
                float ig = sigmoidf_(acc[0][i][d]);
                float fg = sigmoidf_(acc[1][i][d]);
                float gg = tanhf(acc[2][i][d]);
                float og = sigmoidf_(acc[3][i][d]);
                float cn = fmaf(fg, creg[i][d], ig * gg);
                float hv = og * tanhf(cn);
                creg[i][d] = cn;
                hn[d] = hv;
                partial[i] = fmaf(hv, fcw[d], partial[i]);
            }
            // write next-h (STS.128, consecutive 16B per lane -> conflict-free)
            *reinterpret_cast<float4*>(&hs[nxt][(b0 + i) * HIDDEN + j0]) =
                make_float4(hn[0], hn[1], hn[2], hn[3]);
            // warp-level reduction of fc partial (all lanes in a warp share bt)
            float v = partial[i];
            #pragma unroll
            for (int off = 16; off > 0; off >>= 1)
                v += __shfl_xor_sync(0xffffffffu, v, off);
            if ((tid & 31) == 0)
                atomicAdd(&out_s[b0 + i], v);
        }

        __syncthreads();
        if (tid < TB) {
            out[(size_t)t * BATCH + gb0 + tid] = out_s[tid] + fcb;
            out_s[tid] = 0.0f;
        }
        __syncthreads();
        cur = nxt;
    }
}

extern "C" void kernel_launch(void* const* d_in, const int* in_sizes, int n_in,
                              void* d_out, int out_size) {
    const float* x    = (const float*)d_in[0];
    const float* h    = (const float*)d_in[1];
    const float* c    = (const float*)d_in[2];
    const float* W_ih = (const float*)d_in[3];
    const float* W_hh = (const float*)d_in[4];
    const float* b_ih = (const float*)d_in[5];
    const float* b_hh = (const float*)d_in[6];
    const float* fc_W = (const float*)d_in[7];
    const float* fc_b = (const float*)d_in[8];

    transpose_whh<<<(HIDDEN * GATES + 511) / 512, 512>>>(W_hh);
    lstm_fused_kernel<<<BATCH / TB, THREADS>>>(x, h, c, W_ih, b_ih, b_hh,
                                               fc_W, fc_b, (float*)d_out);
}

// round 4
// speedup vs baseline: 1.2192x; 1.2192x over previous
#include <cuda_runtime.h>
#include <math.h>

#define HIDDEN  256
#define GATES   1024        // 4 * HIDDEN
#define HORIZON 24
#define BATCH   32768
#define TB      16          // batch rows per block
#define THREADS 256

// Transposed recurrent weights: WT[k*GATES + r] = W_hh[r*HIDDEN + k]
__device__ float g_WT[HIDDEN * GATES];

__global__ void transpose_whh(const float* __restrict__ W) {
    int idx = blockIdx.x * blockDim.x + threadIdx.x;
    if (idx < HIDDEN * GATES) {
        int k = idx >> 10;          // 0..255
        int r = idx & (GATES - 1);  // 0..1023
        g_WT[idx] = W[r * HIDDEN + k];
    }
}

__device__ __forceinline__ float sigmoidf_(float v) {
    return 1.0f / (1.0f + expf(-v));
}

// ---- packed f32x2 helpers (SASS FFMA2 — only reachable via explicit PTX) ----
__device__ __forceinline__ unsigned long long pack2(float lo, float hi) {
    unsigned long long r;
    asm("mov.b64 %0, {%1, %2};" : "=l"(r) : "f"(lo), "f"(hi));
    return r;
}
__device__ __forceinline__ void unpack2(unsigned long long v, float& lo, float& hi) {
    asm("mov.b64 {%0, %1}, %2;" : "=f"(lo), "=f"(hi) : "l"(v));
}
__device__ __forceinline__ unsigned long long ffma2(unsigned long long a,
                                                    unsigned long long b,
                                                    unsigned long long c) {
    unsigned long long d;
    asm("fma.rn.f32x2 %0, %1, %2, %3;" : "=l"(d) : "l"(a), "l"(b), "l"(c));
    return d;
}

__global__ void __launch_bounds__(THREADS, 1)
lstm_fused_kernel(const float* __restrict__ x,
                  const float* __restrict__ h0,
                  const float* __restrict__ c0,
                  const float* __restrict__ W_ih,
                  const float* __restrict__ b_ih,
                  const float* __restrict__ b_hh,
                  const float* __restrict__ fc_W,
                  const float* __restrict__ fc_b,
                  float* __restrict__ out)
{
    // h double buffer, b-major: hs[buf][b_local*HIDDEN + k]
    __shared__ float hs[2][TB * HIDDEN];
    __shared__ float out_s[TB];

    const int tid = threadIdx.x;
    const int jt  = tid & 63;   // hidden-unit tile index (0..63) -> units 4*jt..4*jt+3
    const int bt  = tid >> 6;   // batch  tile index (0..3)      -> rows  4*bt..4*bt+3
    const int j0  = jt * 4;
    const int b0  = bt * 4;                 // local batch base
    const int gb0 = blockIdx.x * TB;        // global batch base

    // ---- prologue: load h tile into shared (coalesced) ----
    for (int i = tid; i < TB * HIDDEN; i += THREADS)
        hs[0][i] = h0[(size_t)gb0 * HIDDEN + i];
    if (tid < TB) out_s[tid] = 0.0f;

    // ---- per-thread persistent state ----
    float creg[4][4];           // cell state in registers across all steps
    float xv[4];
    #pragma unroll
    for (int i = 0; i < 4; i++) {
        xv[i] = x[gb0 + b0 + i];
        #pragma unroll
        for (int d = 0; d < 4; d++)
            creg[i][d] = c0[(size_t)(gb0 + b0 + i) * HIDDEN + j0 + d];
    }

    // Constant input-path, precomputed ONCE, packed:
    // xg[g][i][p] = pack( x[b0+i]*W_ih[g*H + j0+2p(+1)] + b_ih + b_hh )
    unsigned long long xg[4][4][2];
    #pragma unroll
    for (int g = 0; g < 4; g++) {
        #pragma unroll
        for (int d2 = 0; d2 < 2; d2++) {
            int r = g * HIDDEN + j0 + 2 * d2;
            float w_lo = W_ih[r],     w_hi = W_ih[r + 1];
            float b_lo = b_ih[r]     + b_hh[r];
            float b_hi = b_ih[r + 1] + b_hh[r + 1];
            #pragma unroll
            for (int i = 0; i < 4; i++)
                xg[g][i][d2] = pack2(fmaf(xv[i], w_lo, b_lo),
                                     fmaf(xv[i], w_hi, b_hi));
        }
    }

    float fcw[4];
    #pragma unroll
    for (int d = 0; d < 4; d++) fcw[d] = fc_W[j0 + d];
    const float fcb = fc_b[0];

    __syncthreads();

    const ulonglong2* __restrict__ WT16 = reinterpret_cast<const ulonglong2*>(g_WT);

    int cur = 0;
    for (int t = 0; t < HORIZON; t++) {
        // packed accumulators [gate][batch][d-pair], init = constant input path
        unsigned long long acc2[4][4][2];
        #pragma unroll
        for (int g = 0; g < 4; g++)
            #pragma unroll
            for (int i = 0; i < 4; i++) {
                acc2[g][i][0] = xg[g][i][0];
                acc2[g][i][1] = xg[g][i][1];
            }

        const float* __restrict__ hcur = hs[cur];

        // ---- main GEMM: acc[g][i][d] += WT[k][g*256 + j0+d] * h[b0+i][k] ----
        #pragma unroll 2
        for (int k = 0; k < HIDDEN; k += 4) {
            float ha[4][4];
            #pragma unroll
            for (int i = 0; i < 4; i++) {
                float4 hv = *reinterpret_cast<const float4*>(&hcur[(b0 + i) * HIDDEN + k]);
                ha[i][0] = hv.x; ha[i][1] = hv.y; ha[i][2] = hv.z; ha[i][3] = hv.w;
            }
            #pragma unroll
            for (int kk = 0; kk < 4; kk++) {
                // WT row (k+kk): 16B element index = (k+kk)*256 + g*64 + jt
                const ulonglong2* wr = WT16 + (size_t)(k + kk) * 256 + jt;
                ulonglong2 w0 = wr[0];
                ulonglong2 w1 = wr[64];
                ulonglong2 w2 = wr[128];
                ulonglong2 w3 = wr[192];
                #pragma unroll
                for (int i = 0; i < 4; i++) {
                    unsigned long long hh = pack2(ha[i][kk], ha[i][kk]);
                    acc2[0][i][0] = ffma2(w0.x, hh, acc2[0][i][0]);
                    acc2[0][i][1] = ffma2(w0.y, hh, acc2[0][i][1]);
                    acc2[1][i][0] = ffma2(w1.x, hh, acc2[1][i][0]);
                    acc2[1][i][1] = ffma2(w1.y, hh, acc2[1][i][1]);
                    acc2[2][i][0] = ffma2(w2.x, hh, acc2[2][i][0]);
                    acc2[2][i][1] = ffma2(w2.y, hh, acc2[2][i][1]);
                    acc2[3][i][0] = ffma2(w3.x, hh, acc2[3][i][0]);
                    acc2[3][i][1] = ffma2(w3.y, hh, acc2[3][i][1]);
                }
            }
        }

        // ---- elementwise LSTM cell + fc partial ----
        const int nxt = cur ^ 1;
        #pragma unroll
        for (int i = 0; i < 4; i++) {
            float A[4][4];  // [gate][d]
            #pragma unroll
            for (int g = 0; g < 4; g++) {
                unpack2(acc2[g][i][0], A[g][0], A[g][1]);
                unpack2(acc2[g][i][1], A[g][2], A[g][3]);
            }
            float hn[4];
            float partial = 0.0f;
            #pragma unroll
            for (int d = 0; d < 4; d++) {
                float ig = sigmoidf_(A[0][d]);
                float fg = sigmoidf_(A[1][d]);
                float gg = tanhf(A[2][d]);
                float og = sigmoidf_(A[3][d]);
                float cn = fmaf(fg, creg[i][d], ig * gg);
                float hv = og * tanhf(cn);
                creg[i][d] = cn;
                hn[d] = hv;
                partial = fmaf(hv, fcw[d], partial);
            }
            *reinterpret_cast<float4*>(&hs[nxt][(b0 + i) * HIDDEN + j0]) =
                make_float4(hn[0], hn[1], hn[2], hn[3]);
            float v = partial;
            #pragma unroll
            for (int off = 16; off > 0; off >>= 1)
                v += __shfl_xor_sync(0xffffffffu, v, off);
            if ((tid & 31) == 0)
                atomicAdd(&out_s[b0 + i], v);
        }

        __syncthreads();
        if (tid < TB) {
            out[(size_t)t * BATCH + gb0 + tid] = out_s[tid] + fcb;
            out_s[tid] = 0.0f;
        }
        __syncthreads();
        cur = nxt;
    }
}

extern "C" void kernel_launch(void* const* d_in, const int* in_sizes, int n_in,
                              void* d_out, int out_size) {
    const float* x    = (const float*)d_in[0];
    const float* h    = (const float*)d_in[1];
    const float* c    = (const float*)d_in[2];
    const float* W_ih = (const float*)d_in[3];
    const float* W_hh = (const float*)d_in[4];
    const float* b_ih = (const float*)d_in[5];
    const float* b_hh = (const float*)d_in[6];
    const float* fc_W = (const float*)d_in[7];
    const float* fc_b = (const float*)d_in[8];

    transpose_whh<<<(HIDDEN * GATES + 511) / 512, 512>>>(W_hh);
    lstm_fused_kernel<<<BATCH / TB, THREADS>>>(x, h, c, W_ih, b_ih, b_hh,
                                               fc_W, fc_b, (float*)d_out);
}